// round 17
// baseline (speedup 1.0000x reference)
#include <cuda_runtime.h>
#include <cuda_bf16.h>
#include <cuda_fp16.h>
#include <cstdint>

#define NN 110592
#define CC 128
#define C3 384
#define BB 2
#define GRB 296
#define QK_SMEM ((64 * 136 + 2 * 128 * 20) * 4)

__device__ unsigned g_qkA[(size_t)BB * CC * NN]; // gemm1 q,k out: half2 (q,k) per site
__device__ __half   g_vA [(size_t)BB * CC * NN]; // gemm1 v out (fp16)
__device__ unsigned g_qkB[(size_t)BB * CC * NN]; // dwconv q,k out: half2 (q,k)
__device__ __half   g_vB [(size_t)BB * CC * NN]; // dwconv v out (fp16)
__device__ float g_gram[BB * 8 * 16 * 16];
__device__ float g_ssq [BB * 2 * CC];
__device__ float g_W   [BB * CC * CC];

__device__ __forceinline__ unsigned ph(float lo, float hi) {
    __half2 h = __floats2half2_rn(lo, hi);
    return *(unsigned*)&h;
}
__device__ __forceinline__ void mma16816h(float* d, const unsigned* a, const unsigned* b) {
    asm volatile("mma.sync.aligned.m16n8k16.row.col.f32.f16.f16.f32 "
                 "{%0,%1,%2,%3}, {%4,%5,%6,%7}, {%8,%9}, {%0,%1,%2,%3};"
                 : "+f"(d[0]), "+f"(d[1]), "+f"(d[2]), "+f"(d[3])
                 : "r"(a[0]), "r"(a[1]), "r"(a[2]), "r"(a[3]), "r"(b[0]), "r"(b[1]));
}
__device__ __forceinline__ void ldmx4(unsigned* r, unsigned addr) {
    asm volatile("ldmatrix.sync.aligned.m8n8.x4.shared.b16 {%0,%1,%2,%3}, [%4];"
                 : "=r"(r[0]), "=r"(r[1]), "=r"(r[2]), "=r"(r[3]) : "r"(addr));
}

__global__ void zero_k() {
    int t = blockIdx.x * 256 + threadIdx.x;
    if (t < BB * 8 * 16 * 16) g_gram[t] = 0.f;
    if (t < BB * 2 * CC)      g_ssq[t]  = 0.f;
}

// ------ unified fp16 gemm1: qkv_w @ x. mt 0 -> q halves, mt 1 -> k halves,
//        mt 2 -> vA. B staged ONCE (fp32 -> fp16 k-pairs). -----------------------
__global__ __launch_bounds__(256, 2) void gemm1_k(
    const float* __restrict__ A,
    const float* __restrict__ B, long long bBatch,
    unsigned* __restrict__ qkA, __half* __restrict__ vA)
{
    extern __shared__ unsigned smu[];
    unsigned* sB = smu;                // [64][136]
    unsigned* sA = smu + 64 * 136;     // [2][128][20]
    const int tid = threadIdx.x;
    const int bn = blockIdx.x, bb = blockIdx.y;
    const float* Bb = B + (long long)bb * bBatch + (long long)bn * 128;

    {
        const int k2r = tid >> 5, nq = tid & 31;
        #pragma unroll
        for (int g = 0; g < 8; g++) {
            int k2 = g * 8 + k2r;
            const float* r0 = Bb + (long long)(2 * k2) * NN + nq * 4;
            float4 v0 = *(const float4*)r0;
            float4 v1 = *(const float4*)(r0 + NN);
            *(uint4*)&sB[k2 * 136 + nq * 4] = make_uint4(
                ph(v0.x, v1.x), ph(v0.y, v1.y), ph(v0.z, v1.z), ph(v0.w, v1.w));
        }
    }

    const int ar4 = tid >> 2, aq = tid & 3;
    float4 rgf[4];
    auto ldA = [&](int mt, int kt) {
        const float* At = A + (long long)mt * 16384;
        #pragma unroll
        for (int j = 0; j < 2; j++) {
            const float* p = At + (ar4 + 64 * j) * 128 + kt * 32 + aq * 8;
            rgf[2 * j]     = *(const float4*)p;
            rgf[2 * j + 1] = *(const float4*)(p + 4);
        }
    };
    auto stA = [&](int bufsel) {
        unsigned* base = sA + bufsel * 128 * 20;
        #pragma unroll
        for (int j = 0; j < 2; j++) {
            int m = ar4 + 64 * j;
            float4 u = rgf[2 * j], w = rgf[2 * j + 1];
            *(uint4*)&base[m * 20 + aq * 4] = make_uint4(
                ph(u.x, u.y), ph(u.z, u.w), ph(w.x, w.y), ph(w.z, w.w));
        }
    };

    ldA(0, 0);
    stA(0);
    __syncthreads();

    const int warp = tid >> 5, lane = tid & 31;
    const int wm = warp >> 2, wn = warp & 3;
    const int lr = lane >> 2, lc = lane & 3;

    int buf = 0;
    float acc[4][4][4];
    for (int step = 0; step < 12; step++) {
        const int mt = step >> 2, kt = step & 3;
        if (kt == 0) {
            #pragma unroll
            for (int a = 0; a < 4; a++)
                #pragma unroll
                for (int b2 = 0; b2 < 4; b2++)
                    #pragma unroll
                    for (int r = 0; r < 4; r++) acc[a][b2][r] = 0.f;
        }
        const bool hasNext = (step + 1 < 12);
        if (hasNext) ldA((step + 1) >> 2, (step + 1) & 3);

        const unsigned* sAb = sA + buf * 128 * 20;
        #pragma unroll
        for (int ks = 0; ks < 2; ks++) {
            const int kq = ks * 8;
            const int k2b = kt * 16 + ks * 8;
            unsigned af[4][4], bfr[4][2];
            #pragma unroll
            for (int mi = 0; mi < 4; mi++) {
                int m0 = wm * 64 + mi * 16;
                af[mi][0] = sAb[(m0 + lr) * 20 + kq + lc];
                af[mi][1] = sAb[(m0 + 8 + lr) * 20 + kq + lc];
                af[mi][2] = sAb[(m0 + lr) * 20 + kq + 4 + lc];
                af[mi][3] = sAb[(m0 + 8 + lr) * 20 + kq + 4 + lc];
            }
            #pragma unroll
            for (int ni = 0; ni < 4; ni++) {
                int n0 = wn * 32 + ni * 8;
                bfr[ni][0] = sB[(k2b + lc) * 136 + n0 + lr];
                bfr[ni][1] = sB[(k2b + 4 + lc) * 136 + n0 + lr];
            }
            #pragma unroll
            for (int mi = 0; mi < 4; mi++)
                #pragma unroll
                for (int ni = 0; ni < 4; ni++)
                    mma16816h(acc[mi][ni], af[mi], bfr[ni]);
        }
        if (hasNext) stA(buf ^ 1);
        __syncthreads();
        buf ^= 1;

        if (kt == 3) {
            if (mt < 2) {
                __half* base = (__half*)qkA;
                #pragma unroll
                for (int mi = 0; mi < 4; mi++) {
                    int m0 = wm * 64 + mi * 16;
                    #pragma unroll
                    for (int ni = 0; ni < 4; ni++) {
                        int n0 = wn * 32 + ni * 8;
                        long long i0 = 2 * (((long long)(bb * CC + m0 + lr)) * NN
                                            + bn * 128 + n0 + lc * 2) + mt;
                        long long i1 = 2 * (((long long)(bb * CC + m0 + 8 + lr)) * NN
                                            + bn * 128 + n0 + lc * 2) + mt;
                        base[i0]     = __float2half_rn(acc[mi][ni][0]);
                        base[i0 + 2] = __float2half_rn(acc[mi][ni][1]);
                        base[i1]     = __float2half_rn(acc[mi][ni][2]);
                        base[i1 + 2] = __float2half_rn(acc[mi][ni][3]);
                    }
                }
            } else {
                #pragma unroll
                for (int mi = 0; mi < 4; mi++) {
                    int m0 = wm * 64 + mi * 16;
                    #pragma unroll
                    for (int ni = 0; ni < 4; ni++) {
                        int n0 = wn * 32 + ni * 8;
                        long long r0 = (long long)(bb * CC + m0 + lr) * NN
                                     + bn * 128 + n0 + lc * 2;
                        long long r1 = (long long)(bb * CC + m0 + 8 + lr) * NN
                                     + bn * 128 + n0 + lc * 2;
                        *(__half2*)(vA + r0) = __floats2half2_rn(acc[mi][ni][0], acc[mi][ni][1]);
                        *(__half2*)(vA + r1) = __floats2half2_rn(acc[mi][ni][2], acc[mi][ni][3]);
                    }
                }
            }
        }
    }
}

// ------ fp16 GEMM (single tile) for gemm2: W(fp32 cvt) @ vB(fp16) -> fp32 -------
__global__ __launch_bounds__(256, 2) void gemm2_k(
    const float* __restrict__ A, long long aBatch,
    const __half* __restrict__ B, long long bBatch,
    float* __restrict__ C, long long cBatch)
{
    extern __shared__ unsigned smu[];
    unsigned* sB = smu;
    unsigned* sA = smu + 64 * 136;
    const int tid = threadIdx.x;
    const int bn = blockIdx.x, bb = blockIdx.y;
    const float* Ab = A + (long long)bb * aBatch;
    const __half* Bb = B + (long long)bb * bBatch + (long long)bn * 128;

    {
        const int k2r = tid >> 5, nq = tid & 31;
        #pragma unroll
        for (int g = 0; g < 8; g++) {
            int k2 = g * 8 + k2r;
            const uint2* r0 = (const uint2*)(Bb + (long long)(2 * k2) * NN + nq * 4);
            const uint2* r1 = (const uint2*)(Bb + (long long)(2 * k2 + 1) * NN + nq * 4);
            uint2 u = *r0, v = *r1;
            *(uint4*)&sB[k2 * 136 + nq * 4] = make_uint4(
                __byte_perm(u.x, v.x, 0x5410), __byte_perm(u.x, v.x, 0x7632),
                __byte_perm(u.y, v.y, 0x5410), __byte_perm(u.y, v.y, 0x7632));
        }
    }

    const int ar4 = tid >> 2, aq = tid & 3;
    float4 rgf[4];
    auto ldA = [&](int kt) {
        #pragma unroll
        for (int j = 0; j < 2; j++) {
            const float* p = Ab + (ar4 + 64 * j) * 128 + kt * 32 + aq * 8;
            rgf[2 * j]     = *(const float4*)p;
            rgf[2 * j + 1] = *(const float4*)(p + 4);
        }
    };
    auto stA = [&](int bufsel) {
        unsigned* base = sA + bufsel * 128 * 20;
        #pragma unroll
        for (int j = 0; j < 2; j++) {
            int m = ar4 + 64 * j;
            float4 u = rgf[2 * j], w = rgf[2 * j + 1];
            *(uint4*)&base[m * 20 + aq * 4] = make_uint4(
                ph(u.x, u.y), ph(u.z, u.w), ph(w.x, w.y), ph(w.z, w.w));
        }
    };

    ldA(0);
    stA(0);
    __syncthreads();

    const int warp = tid >> 5, lane = tid & 31;
    const int wm = warp >> 2, wn = warp & 3;
    const int lr = lane >> 2, lc = lane & 3;

    int buf = 0;
    float acc[4][4][4];
    #pragma unroll
    for (int a = 0; a < 4; a++)
        #pragma unroll
        for (int b2 = 0; b2 < 4; b2++)
            #pragma unroll
            for (int r = 0; r < 4; r++) acc[a][b2][r] = 0.f;

    for (int kt = 0; kt < 4; kt++) {
        const bool hasNext = (kt + 1 < 4);
        if (hasNext) ldA(kt + 1);

        const unsigned* sAb = sA + buf * 128 * 20;
        #pragma unroll
        for (int ks = 0; ks < 2; ks++) {
            const int kq = ks * 8;
            const int k2b = kt * 16 + ks * 8;
            unsigned af[4][4], bfr[4][2];
            #pragma unroll
            for (int mi = 0; mi < 4; mi++) {
                int m0 = wm * 64 + mi * 16;
                af[mi][0] = sAb[(m0 + lr) * 20 + kq + lc];
                af[mi][1] = sAb[(m0 + 8 + lr) * 20 + kq + lc];
                af[mi][2] = sAb[(m0 + lr) * 20 + kq + 4 + lc];
                af[mi][3] = sAb[(m0 + 8 + lr) * 20 + kq + 4 + lc];
            }
            #pragma unroll
            for (int ni = 0; ni < 4; ni++) {
                int n0 = wn * 32 + ni * 8;
                bfr[ni][0] = sB[(k2b + lc) * 136 + n0 + lr];
                bfr[ni][1] = sB[(k2b + 4 + lc) * 136 + n0 + lr];
            }
            #pragma unroll
            for (int mi = 0; mi < 4; mi++)
                #pragma unroll
                for (int ni = 0; ni < 4; ni++)
                    mma16816h(acc[mi][ni], af[mi], bfr[ni]);
        }
        if (hasNext) stA(buf ^ 1);
        __syncthreads();
        buf ^= 1;
    }

    float* Cb = C + (long long)bb * cBatch + (long long)bn * 128;
    #pragma unroll
    for (int mi = 0; mi < 4; mi++) {
        int m0 = wm * 64 + mi * 16;
        #pragma unroll
        for (int ni = 0; ni < 4; ni++) {
            int n0 = wn * 32 + ni * 8;
            long long r0 = (long long)(m0 + lr) * NN + n0 + lc * 2;
            long long r1 = (long long)(m0 + 8 + lr) * NN + n0 + lc * 2;
            *(float2*)(Cb + r0) = make_float2(acc[mi][ni][0], acc[mi][ni][1]);
            *(float2*)(Cb + r1) = make_float2(acc[mi][ni][2], acc[mi][ni][3]);
        }
    }
}

// ------ depthwise 3x3x3. cu<128: (q,k) half2 pair, HFMA2. cu>=128: v fp32 path. -
__global__ __launch_bounds__(192, 4) void dwconv_k(
    const unsigned* __restrict__ qk_in, const __half* __restrict__ v_in,
    const float* __restrict__ wg,
    unsigned* __restrict__ qk_out, __half* __restrict__ v_out)
{
    __shared__ float sP[4][50 * 60];
    __shared__ float2 sred[192];
    const int hhalf = blockIdx.x, cu = blockIdx.y, b = blockIdx.z;
    const int tx = threadIdx.x, ty = threadIdx.y;
    const int tid = ty * 48 + tx;
    const int h0 = hhalf * 24;
    const bool isQK = (cu < 128);

    for (int i = tid; i < 4 * 3000; i += 192) ((float*)sP)[i] = 0.f;

    __half2 wv2[27];
    float wv[27];
    if (isQK) {
        const float* wq = wg + cu * 27;
        const float* wk = wg + (cu + 128) * 27;
        #pragma unroll
        for (int i = 0; i < 27; i++) wv2[i] = __floats2half2_rn(wq[i], wk[i]);
    } else {
        const float* wp = wg + (cu + 128) * 27;   // cu 128..255 -> channel 256..383
        #pragma unroll
        for (int i = 0; i < 27; i++) wv[i] = wp[i];
    }
    __syncthreads();

    const float* qbase = (const float*)qk_in + (long long)(b * CC + cu) * NN;
    const __half* vbase = v_in + (long long)(b * CC + (cu - 128)) * NN;

    auto loadPlane = [&](int slot, int hh) {
        float* sp = sP[slot];
        if (isQK) {
            const float* pl = qbase + (long long)hh * 2304;
            #pragma unroll
            for (int j = 0; j < 3; j++) {
                int l = j * 192 + tid;
                int wr = l / 12, q = l % 12;
                float4 v = *(const float4*)(pl + wr * 48 + q * 4);
                *(float4*)(&sp[(wr + 1) * 60 + 4 + q * 4]) = v;
            }
        } else {
            const __half2* pl = (const __half2*)(vbase + (long long)hh * 2304);
            #pragma unroll
            for (int j = 0; j < 6; j++) {
                int l = j * 192 + tid;
                int wr = l / 24, cp = l % 24;
                float2 f = __half22float2(pl[l]);
                *(float2*)(&sp[(wr + 1) * 60 + 4 + cp * 2]) = f;
            }
        }
    };
    auto zeroPlane = [&](int slot) {
        float* sp = sP[slot];
        for (int i = tid; i < 3000; i += 192) sp[i] = 0.f;
    };

    if (h0 - 1 >= 0) loadPlane(h0 & 3, h0 - 1);
    loadPlane((h0 + 1) & 3, h0);

    const int d = tx, w0 = ty * 12;
    float2 lssq = make_float2(0.f, 0.f);
    unsigned* qob0 = qk_out + (long long)(b * CC + cu) * NN;
    __half* vob0 = v_out + (long long)(b * CC + (cu - 128)) * NN;

    for (int h = h0; h < h0 + 24; h++) {
        if (h + 1 < 48) loadPlane((h + 2) & 3, h + 1);
        else            zeroPlane((h + 2) & 3);
        __syncthreads();
        const float* P0 = sP[h & 3];
        const float* P1 = sP[(h + 1) & 3];
        const float* P2 = sP[(h + 2) & 3];

        float r[3][3][3];   // taps: fp32 for v, raw half2 bits for qk
        #pragma unroll
        for (int dp = 0; dp < 3; dp++) {
            r[0][0][dp] = P0[w0 * 60 + d + 3 + dp];
            r[0][1][dp] = P1[w0 * 60 + d + 3 + dp];
            r[0][2][dp] = P2[w0 * 60 + d + 3 + dp];
            r[1][0][dp] = P0[(w0 + 1) * 60 + d + 3 + dp];
            r[1][1][dp] = P1[(w0 + 1) * 60 + d + 3 + dp];
            r[1][2][dp] = P2[(w0 + 1) * 60 + d + 3 + dp];
        }
        const long long rowoff = (long long)h * 2304;
        #pragma unroll
        for (int k = 0; k < 12; k++) {
            const int ns = (k + 2) % 3;
            #pragma unroll
            for (int dp = 0; dp < 3; dp++) {
                r[ns][0][dp] = P0[(w0 + k + 2) * 60 + d + 3 + dp];
                r[ns][1][dp] = P1[(w0 + k + 2) * 60 + d + 3 + dp];
                r[ns][2][dp] = P2[(w0 + k + 2) * 60 + d + 3 + dp];
            }
            const long long off = rowoff + (w0 + k) * 48 + d;
            if (isQK) {
                __half2 o = __floats2half2_rn(0.f, 0.f);
                #pragma unroll
                for (int hp = 0; hp < 3; hp++)
                    #pragma unroll
                    for (int q = 0; q < 3; q++) {
                        const int sl = (k + q) % 3;
                        #pragma unroll
                        for (int dp = 0; dp < 3; dp++)
                            o = __hfma2(wv2[hp * 9 + q * 3 + dp],
                                        *(const __half2*)&r[sl][hp][dp], o);
                    }
                float2 of = __half22float2(o);
                lssq.x += of.x * of.x;
                lssq.y += of.y * of.y;
                qob0[off] = *(unsigned*)&o;
            } else {
                float o = 0.f;
                #pragma unroll
                for (int hp = 0; hp < 3; hp++)
                    #pragma unroll
                    for (int q = 0; q < 3; q++) {
                        const int sl = (k + q) % 3;
                        #pragma unroll
                        for (int dp = 0; dp < 3; dp++)
                            o += wv[hp * 9 + q * 3 + dp] * r[sl][hp][dp];
                    }
                vob0[off] = __float2half_rn(o);
            }
        }
    }

    if (isQK) {
        sred[tid] = lssq;
        __syncthreads();
        if (tid < 32) {
            float2 v = sred[tid];
            #pragma unroll
            for (int j = 1; j < 6; j++) {
                v.x += sred[tid + j * 32].x;
                v.y += sred[tid + j * 32].y;
            }
            #pragma unroll
            for (int off = 16; off > 0; off >>= 1) {
                v.x += __shfl_down_sync(0xffffffffu, v.x, off);
                v.y += __shfl_down_sync(0xffffffffu, v.y, off);
            }
            if (tid == 0) {
                atomicAdd(&g_ssq[b * 256 + cu], v.x);
                atomicAdd(&g_ssq[b * 256 + 128 + cu], v.y);
            }
        }
    }
}

// ------ Gram via fp16 tensor cores, interleaved (q,k) input ---------------------
__global__ __launch_bounds__(256) void gram_k(const unsigned* __restrict__ qk) {
    __shared__ __half sq[256 * 40];
    const int tid = threadIdx.x;
    const int b = blockIdx.y;
    const int warp = tid >> 5, lane = tid & 31;
    const unsigned* qkb = qk + (long long)b * CC * NN;
    const int pr = tid >> 1, nh = tid & 1;

    uint4 rg[4];
    auto ldC = [&](int c) {
        const uint4* p = (const uint4*)(qkb + (long long)pr * NN + c * 32 + nh * 16);
        #pragma unroll
        for (int j = 0; j < 4; j++) rg[j] = p[j];
    };
    auto stC = [&]() {
        #pragma unroll
        for (int j = 0; j < 4; j++) {
            uint4 u = rg[j];
            unsigned q0 = __byte_perm(u.x, u.y, 0x5410);
            unsigned q1 = __byte_perm(u.z, u.w, 0x5410);
            unsigned k0 = __byte_perm(u.x, u.y, 0x7632);
            unsigned k1 = __byte_perm(u.z, u.w, 0x7632);
            int nb = nh * 16 + j * 4;
            *(uint2*)&sq[pr * 40 + nb]         = make_uint2(q0, q1);
            *(uint2*)&sq[(128 + pr) * 40 + nb] = make_uint2(k0, k1);
        }
    };

    const int h = warp;
    const int aRow = h * 16 + (lane & 7) + ((lane >> 3) & 1) * 8;
    const unsigned aAddr = (unsigned)__cvta_generic_to_shared(&sq[aRow * 40])
                         + ((lane >> 4) & 1) * 16;
    const int bRow = 128 + h * 16 + (lane & 7) + ((lane >> 4) & 1) * 8;
    const unsigned bAddr = (unsigned)__cvta_generic_to_shared(&sq[bRow * 40])
                         + ((lane >> 3) & 1) * 16;

    float acc[2][4];
    #pragma unroll
    for (int jh = 0; jh < 2; jh++)
        #pragma unroll
        for (int r = 0; r < 4; r++) acc[jh][r] = 0.f;

    int c = blockIdx.x;
    ldC(c);
    while (1) {
        stC();
        __syncthreads();
        int cn = c + GRB;
        bool more = cn < NN / 32;
        if (more) ldC(cn);
        #pragma unroll
        for (int ks = 0; ks < 2; ks++) {
            unsigned a[4], bb2[4];
            ldmx4(a, aAddr + ks * 32);
            ldmx4(bb2, bAddr + ks * 32);
            mma16816h(acc[0], a, bb2 + 0);
            mma16816h(acc[1], a, bb2 + 2);
        }
        __syncthreads();
        if (!more) break;
        c = cn;
    }

    const int row = lane >> 2, col = (lane & 3) * 2;
    float* G = &g_gram[(b * 8 + h) * 256];
    #pragma unroll
    for (int jh = 0; jh < 2; jh++) {
        const int j0 = jh * 8 + col;
        atomicAdd(&G[row * 16 + j0],           acc[jh][0]);
        atomicAdd(&G[row * 16 + j0 + 1],       acc[jh][1]);
        atomicAdd(&G[(row + 8) * 16 + j0],     acc[jh][2]);
        atomicAdd(&G[(row + 8) * 16 + j0 + 1], acc[jh][3]);
    }
}

// ------ softmax + W_b = proj_w @ blockdiag(attn_b) ------------------------------
__global__ __launch_bounds__(256) void fold_k(
    const float* __restrict__ proj_w, const float* __restrict__ temp)
{
    __shared__ float sat[8][16][17];
    const int b = blockIdx.x, tid = threadIdx.x;
    if (tid < 128) {
        const int h = tid >> 4, i = tid & 15;
        float nq = fmaxf(sqrtf(g_ssq[b * 256 + h * 16 + i]), 1e-12f);
        float tv = temp[h];
        float row[16];
        float mx = -1e30f;
        #pragma unroll
        for (int j = 0; j < 16; j++) {
            float nk = fmaxf(sqrtf(g_ssq[b * 256 + 128 + h * 16 + j]), 1e-12f);
            float v = g_gram[((b * 8 + h) * 16 + i) * 16 + j] / (nq * nk) * tv;
            row[j] = v;
            mx = fmaxf(mx, v);
        }
        float s = 0.f;
        #pragma unroll
        for (int j = 0; j < 16; j++) { row[j] = expf(row[j] - mx); s += row[j]; }
        const float inv = 1.f / s;
        #pragma unroll
        for (int j = 0; j < 16; j++) sat[h][i][j] = row[j] * inv;
    }
    __syncthreads();
    for (int idx = tid; idx < 16384; idx += 256) {
        const int o = idx >> 7, col = idx & 127;
        const int h = col >> 4, j = col & 15;
        float s = 0.f;
        #pragma unroll
        for (int i = 0; i < 16; i++)
            s += proj_w[o * 128 + h * 16 + i] * sat[h][i][j];
        g_W[b * 16384 + idx] = s;
    }
}

extern "C" void kernel_launch(void* const* d_in, const int* in_sizes, int n_in,
                              void* d_out, int out_size) {
    const float* x      = (const float*)d_in[0];
    const float* qkv_w  = (const float*)d_in[1];
    const float* dw_w   = (const float*)d_in[2];
    const float* proj_w = (const float*)d_in[3];
    const float* temp   = (const float*)d_in[4];
    float* out = (float*)d_out;

    void *p_qkA = nullptr, *p_vA = nullptr, *p_qkB = nullptr, *p_vB = nullptr, *p_W = nullptr;
    cudaGetSymbolAddress(&p_qkA, g_qkA);
    cudaGetSymbolAddress(&p_vA,  g_vA);
    cudaGetSymbolAddress(&p_qkB, g_qkB);
    cudaGetSymbolAddress(&p_vB,  g_vB);
    cudaGetSymbolAddress(&p_W,   g_W);

    cudaFuncSetAttribute(gemm1_k, cudaFuncAttributeMaxDynamicSharedMemorySize, QK_SMEM);
    cudaFuncSetAttribute(gemm2_k, cudaFuncAttributeMaxDynamicSharedMemorySize, QK_SMEM);

    zero_k<<<16, 256>>>();

    // q,k -> interleaved half2 pairs; v -> fp16 (B staged once)
    gemm1_k<<<dim3(NN / 128, BB), 256, QK_SMEM>>>(
        qkv_w, x, (long long)CC * NN,
        (unsigned*)p_qkA, (__half*)p_vA);

    dwconv_k<<<dim3(2, 256, BB), dim3(48, 4)>>>(
        (const unsigned*)p_qkA, (const __half*)p_vA, dw_w,
        (unsigned*)p_qkB, (__half*)p_vB);

    gram_k<<<dim3(GRB, BB), 256>>>((const unsigned*)p_qkB);

    fold_k<<<BB, 256>>>(proj_w, temp);

    gemm2_k<<<dim3(NN / 128, BB), 256, QK_SMEM>>>(
        (const float*)p_W, (long long)CC * CC,
        (const __half*)p_vB, (long long)CC * NN,
        out, (long long)CC * NN);
}